// round 3
// baseline (speedup 1.0000x reference)
#include <cuda_runtime.h>

#define B_   4
#define T_   1024
#define NX_  1024
#define NH_  16
#define HD_  64

// Scratch (static device globals: allocation-free per harness rules)
// [B, H, T, D] layouts; 16 MB each.
__device__ float g_q  [B_ * NH_ * T_ * HD_];
__device__ float g_k  [B_ * NH_ * T_ * HD_];
__device__ float g_v  [B_ * NH_ * T_ * HD_];
__device__ float g_ret[B_ * NH_ * T_ * HD_];

// ---------------------------------------------------------------------------
// GEMM 1: qkv = x @ w_attn + b_attn, scattered into g_q/g_k/g_v [B,H,T,D]
// M=4096 (b*1024+t), N=3072, K=1024. 128x128x8 tiles, 256 thr, 8x8/thread.
// Double-buffered smem: 1 barrier per K-step, gmem prefetch overlapped
// with the FFMA block.
// ---------------------------------------------------------------------------
__global__ __launch_bounds__(256) void qkv_gemm(const float* __restrict__ X,
                                                const float* __restrict__ W,
                                                const float* __restrict__ bias)
{
    __shared__ float As[2][8][128];
    __shared__ float Bs[2][8][128];

    const int tid = threadIdx.x;
    const int tx = tid & 15, ty = tid >> 4;
    const int m0 = blockIdx.y * 128, n0 = blockIdx.x * 128;

    const int arow = tid >> 1;            // 0..127
    const int ak4  = (tid & 1) * 4;       // 0 or 4
    const int brow = tid >> 5;            // 0..7
    const int bc4  = (tid & 31) * 4;      // 0..124

    const float* aptr = &X[(m0 + arow) * 1024 + ak4];
    const float* bptr = &W[brow * 3072 + n0 + bc4];

    float acc[8][8];
    #pragma unroll
    for (int i = 0; i < 8; i++)
        #pragma unroll
        for (int j = 0; j < 8; j++) acc[i][j] = 0.f;

    // prologue: load k-tile 0 into buffer 0
    {
        float4 av = *(const float4*)(aptr);
        float4 bv = *(const float4*)(bptr);
        As[0][ak4 + 0][arow] = av.x;
        As[0][ak4 + 1][arow] = av.y;
        As[0][ak4 + 2][arow] = av.z;
        As[0][ak4 + 3][arow] = av.w;
        *(float4*)&Bs[0][brow][bc4] = bv;
    }
    __syncthreads();

    int cur = 0;
    for (int k0 = 0; k0 < 1024; k0 += 8) {
        const int nxt = cur ^ 1;
        float4 av2, bv2;
        const bool has = (k0 + 8) < 1024;
        if (has) {
            av2 = *(const float4*)(aptr + (k0 + 8));
            bv2 = *(const float4*)(bptr + (k0 + 8) * 3072);
        }

        #pragma unroll
        for (int kk = 0; kk < 8; kk++) {
            float a[8], b[8];
            *(float4*)(a)     = *(const float4*)&As[cur][kk][ty * 8];
            *(float4*)(a + 4) = *(const float4*)&As[cur][kk][ty * 8 + 4];
            *(float4*)(b)     = *(const float4*)&Bs[cur][kk][tx * 8];
            *(float4*)(b + 4) = *(const float4*)&Bs[cur][kk][tx * 8 + 4];
            #pragma unroll
            for (int i = 0; i < 8; i++)
                #pragma unroll
                for (int j = 0; j < 8; j++) acc[i][j] += a[i] * b[j];
        }

        if (has) {
            As[nxt][ak4 + 0][arow] = av2.x;
            As[nxt][ak4 + 1][arow] = av2.y;
            As[nxt][ak4 + 2][arow] = av2.z;
            As[nxt][ak4 + 3][arow] = av2.w;
            *(float4*)&Bs[nxt][brow][bc4] = bv2;
        }
        __syncthreads();
        cur = nxt;
    }

    #pragma unroll
    for (int i = 0; i < 8; i++) {
        const int m = m0 + ty * 8 + i;
        const int b = m >> 10, t = m & 1023;
        #pragma unroll
        for (int j = 0; j < 8; j++) {
            const int n = n0 + tx * 8 + j;
            float c = acc[i][j] + bias[n];
            const int which = n >> 10;
            const int rem = n & 1023;
            const int h = rem >> 6, d = rem & 63;
            float* dst = (which == 0) ? g_q : (which == 1) ? g_k : g_v;
            dst[((b * NH_ + h) * T_ + t) * HD_ + d] = c;
        }
    }
}

// ---------------------------------------------------------------------------
// GEMM 2: out = ret_transposed @ w_proj + b_proj
// A gathered from g_ret [B,H,T,D] with k = h*64+d. M=4096, N=1024, K=1024.
// Same double-buffered structure.
// ---------------------------------------------------------------------------
__global__ __launch_bounds__(256) void proj_gemm(const float* __restrict__ W,
                                                 const float* __restrict__ bias,
                                                 float* __restrict__ out)
{
    __shared__ float As[2][8][128];
    __shared__ float Bs[2][8][128];

    const int tid = threadIdx.x;
    const int tx = tid & 15, ty = tid >> 4;
    const int m0 = blockIdx.y * 128, n0 = blockIdx.x * 128;

    const int arow = tid >> 1;
    const int ak4  = (tid & 1) * 4;
    const int brow = tid >> 5;
    const int bc4  = (tid & 31) * 4;

    const int mrow = m0 + arow;
    const int ab = mrow >> 10, at = mrow & 1023;
    // k = h*64 + d ; 4 consecutive d never cross an h boundary
    const float* aret = &g_ret[(ab * NH_ * T_ + at) * HD_];  // + h*T_*HD_ + d
    const float* bptr = &W[brow * 1024 + n0 + bc4];

    float acc[8][8];
    #pragma unroll
    for (int i = 0; i < 8; i++)
        #pragma unroll
        for (int j = 0; j < 8; j++) acc[i][j] = 0.f;

    {
        const int k = ak4;
        const int h = k >> 6, d = k & 63;
        float4 av = *(const float4*)&aret[h * T_ * HD_ + d];
        float4 bv = *(const float4*)(bptr);
        As[0][ak4 + 0][arow] = av.x;
        As[0][ak4 + 1][arow] = av.y;
        As[0][ak4 + 2][arow] = av.z;
        As[0][ak4 + 3][arow] = av.w;
        *(float4*)&Bs[0][brow][bc4] = bv;
    }
    __syncthreads();

    int cur = 0;
    for (int k0 = 0; k0 < 1024; k0 += 8) {
        const int nxt = cur ^ 1;
        float4 av2, bv2;
        const bool has = (k0 + 8) < 1024;
        if (has) {
            const int k = k0 + 8 + ak4;
            const int h = k >> 6, d = k & 63;
            av2 = *(const float4*)&aret[h * T_ * HD_ + d];
            bv2 = *(const float4*)(bptr + (k0 + 8) * 1024);
        }

        #pragma unroll
        for (int kk = 0; kk < 8; kk++) {
            float a[8], b[8];
            *(float4*)(a)     = *(const float4*)&As[cur][kk][ty * 8];
            *(float4*)(a + 4) = *(const float4*)&As[cur][kk][ty * 8 + 4];
            *(float4*)(b)     = *(const float4*)&Bs[cur][kk][tx * 8];
            *(float4*)(b + 4) = *(const float4*)&Bs[cur][kk][tx * 8 + 4];
            #pragma unroll
            for (int i = 0; i < 8; i++)
                #pragma unroll
                for (int j = 0; j < 8; j++) acc[i][j] += a[i] * b[j];
        }

        if (has) {
            As[nxt][ak4 + 0][arow] = av2.x;
            As[nxt][ak4 + 1][arow] = av2.y;
            As[nxt][ak4 + 2][arow] = av2.z;
            As[nxt][ak4 + 3][arow] = av2.w;
            *(float4*)&Bs[nxt][brow][bc4] = bv2;
        }
        __syncthreads();
        cur = nxt;
    }

    #pragma unroll
    for (int i = 0; i < 8; i++) {
        const int m = m0 + ty * 8 + i;
        #pragma unroll
        for (int j = 0; j < 8; j++) {
            const int n = n0 + tx * 8 + j;
            out[m * 1024 + n] = acc[i][j] + bias[n];
        }
    }
}

// ---------------------------------------------------------------------------
// Flash attention with relative bias + bucketed relative-values term.
// One CTA per (t-block of 64, head, batch). 256 threads = 16x16, 4x4/thread.
// Online softmax; 64-bucket mass accumulator for the rel_values einsum:
//   ret2[t,d] = sum_s p[t,s] * relV[relIds[t,s], d]
//             = sum_r mass[t,r] * relV[r,d],  mass[t,r] = sum_{s:ids=r} p[t,s]
// mass rows are PRIVATE per half-warp (row = ty*4+i), so only __syncwarp
// is needed around the P/mass exchange.
// ---------------------------------------------------------------------------
#define SSTR 65   // padded smem row stride (bank-conflict mitigation)

__global__ __launch_bounds__(256) void attn_kernel(const int*   __restrict__ relB,
                                                   const float* __restrict__ relW,
                                                   const float* __restrict__ relV,
                                                   const int*   __restrict__ relIds)
{
    extern __shared__ float sm[];
    float* Qs   = sm;                 // 64 x SSTR
    float* KP   = Qs  + 64 * SSTR;    // K tile, then reused for P tile / relV
    float* Vs   = KP  + 64 * SSTR;    // 64 x SSTR
    float* mass = Vs  + 64 * SSTR;    // 64 rows x 64 buckets (SSTR stride)
    float* relw = mass + 64 * SSTR;   // 64  (rel_weights column for this head)
    float* m_s  = relw + 64;          // 64
    float* l_s  = m_s + 64;           // 64
    float* sc_s = l_s + 64;           // 64

    const int tid = threadIdx.x;
    const int tx = tid & 15, ty = tid >> 4;
    const int jb = blockIdx.x;        // t-block
    const int h  = blockIdx.y;
    const int b  = blockIdx.z;
    const int tbase = jb * 64;

    const int headoff = ((b * NH_ + h) * T_) * HD_;
    const float* qptr = g_q + headoff;
    const float* kptr = g_k + headoff;
    const float* vptr = g_v + headoff;

    // init
    for (int it = tid; it < 64 * SSTR; it += 256) mass[it] = 0.f;
    if (tid < 64) {
        m_s[tid] = -1e30f;
        l_s[tid] = 0.f;
        relw[tid] = relW[tid * NH_ + h];
    }
    // load Q tile (64x64)
    for (int it = tid; it < 64 * 16; it += 256) {
        const int r = it >> 4, c = (it & 15) * 4;
        float4 v = *(const float4*)&qptr[(tbase + r) * HD_ + c];
        Qs[r * SSTR + c + 0] = v.x;
        Qs[r * SSTR + c + 1] = v.y;
        Qs[r * SSTR + c + 2] = v.z;
        Qs[r * SSTR + c + 3] = v.w;
    }

    float acc[4][4];
    #pragma unroll
    for (int i = 0; i < 4; i++)
        #pragma unroll
        for (int j = 0; j < 4; j++) acc[i][j] = 0.f;

    for (int sb = 0; sb <= jb; sb++) {
        const int sbase = sb * 64;
        __syncthreads();   // previous iteration's P/V reads done; init done

        // load K, V tiles
        for (int it = tid; it < 64 * 16; it += 256) {
            const int r = it >> 4, c = (it & 15) * 4;
            float4 kv = *(const float4*)&kptr[(sbase + r) * HD_ + c];
            float4 vv = *(const float4*)&vptr[(sbase + r) * HD_ + c];
            KP[r * SSTR + c + 0] = kv.x; KP[r * SSTR + c + 1] = kv.y;
            KP[r * SSTR + c + 2] = kv.z; KP[r * SSTR + c + 3] = kv.w;
            Vs[r * SSTR + c + 0] = vv.x; Vs[r * SSTR + c + 1] = vv.y;
            Vs[r * SSTR + c + 2] = vv.z; Vs[r * SSTR + c + 3] = vv.w;
        }
        __syncthreads();

        // S = Q K^T   (raw dot)
        float s[4][4];
        #pragma unroll
        for (int i = 0; i < 4; i++)
            #pragma unroll
            for (int j = 0; j < 4; j++) s[i][j] = 0.f;

        #pragma unroll 8
        for (int d = 0; d < 64; d++) {
            float q[4], k[4];
            #pragma unroll
            for (int i = 0; i < 4; i++) q[i] = Qs[(ty * 4 + i) * SSTR + d];
            #pragma unroll
            for (int j = 0; j < 4; j++) k[j] = KP[(tx * 4 + j) * SSTR + d];
            #pragma unroll
            for (int i = 0; i < 4; i++)
                #pragma unroll
                for (int j = 0; j < 4; j++) s[i][j] += q[i] * k[j];
        }
        __syncthreads();   // everyone done reading K; KP now free for P

        // scale + relative bias + causal mask  (vectorized int4 gathers)
        #pragma unroll
        for (int i = 0; i < 4; i++) {
            const int t = tbase + ty * 4 + i;
            const int4 rb = *(const int4*)&relB[(b * T_ + t) * T_ + sbase + tx * 4];
            const int rbv[4] = {rb.x, rb.y, rb.z, rb.w};
            #pragma unroll
            for (int j = 0; j < 4; j++) {
                const int sg = sbase + tx * 4 + j;
                if (sg <= t)
                    s[i][j] = s[i][j] * 0.125f + relw[rbv[j]];
                else
                    s[i][j] = -1e30f;
            }
        }

        // row max (across 16 tx lanes, half-warp segments)
        float rmax[4];
        #pragma unroll
        for (int i = 0; i < 4; i++) {
            float v = s[i][0];
            v = fmaxf(v, s[i][1]); v = fmaxf(v, s[i][2]); v = fmaxf(v, s[i][3]);
            rmax[i] = v;
        }
        #pragma unroll
        for (int o = 8; o >= 1; o >>= 1)
            #pragma unroll
            for (int i = 0; i < 4; i++)
                rmax[i] = fmaxf(rmax[i], __shfl_xor_sync(0xffffffffu, rmax[i], o, 16));

        if (tx == 0) {
            #pragma unroll
            for (int i = 0; i < 4; i++) {
                const int r = ty * 4 + i;
                float mn = fmaxf(m_s[r], rmax[i]);
                sc_s[r] = __expf(m_s[r] - mn);
                m_s[r] = mn;
            }
        }
        __syncwarp();

        // exponentiate + row sums
        float rsum[4];
        #pragma unroll
        for (int i = 0; i < 4; i++) {
            const float mi = m_s[ty * 4 + i];
            float acc_s = 0.f;
            #pragma unroll
            for (int j = 0; j < 4; j++) {
                float p = __expf(s[i][j] - mi);
                s[i][j] = p;
                acc_s += p;
            }
            rsum[i] = acc_s;
        }
        #pragma unroll
        for (int o = 8; o >= 1; o >>= 1)
            #pragma unroll
            for (int i = 0; i < 4; i++)
                rsum[i] += __shfl_xor_sync(0xffffffffu, rsum[i], o, 16);

        if (tx == 0) {
            #pragma unroll
            for (int i = 0; i < 4; i++) {
                const int r = ty * 4 + i;
                l_s[r] = l_s[r] * sc_s[r] + rsum[i];
            }
        }

        // rescale output accumulator and mass buckets
        #pragma unroll
        for (int i = 0; i < 4; i++) {
            const float sc = sc_s[ty * 4 + i];
            #pragma unroll
            for (int j = 0; j < 4; j++) {
                acc[i][j] *= sc;
                mass[(ty * 4 + i) * SSTR + tx * 4 + j] *= sc;
            }
        }

        // write P into KP
        #pragma unroll
        for (int i = 0; i < 4; i++)
            #pragma unroll
            for (int j = 0; j < 4; j++)
                KP[(ty * 4 + i) * SSTR + tx * 4 + j] = s[i][j];
        __syncwarp();   // P visible + mass scaling done within half-warp

        // bucket accumulation for rel_values term (int4 gather of ids)
        #pragma unroll
        for (int i = 0; i < 4; i++) {
            const int t = tbase + ty * 4 + i;
            const int4 ri = *(const int4*)&relIds[t * T_ + sbase + tx * 4];
            const int riv[4] = {ri.x, ri.y, ri.z, ri.w};
            #pragma unroll
            for (int j = 0; j < 4; j++) {
                const int sg = sbase + tx * 4 + j;
                if (sg <= t)
                    atomicAdd(&mass[(ty * 4 + i) * SSTR + riv[j]], s[i][j]);
            }
        }

        // acc += P @ V
        #pragma unroll 8
        for (int ss = 0; ss < 64; ss++) {
            float p[4], v[4];
            #pragma unroll
            for (int i = 0; i < 4; i++) p[i] = KP[(ty * 4 + i) * SSTR + ss];
            #pragma unroll
            for (int j = 0; j < 4; j++) v[j] = Vs[ss * SSTR + tx * 4 + j];
            #pragma unroll
            for (int i = 0; i < 4; i++)
                #pragma unroll
                for (int j = 0; j < 4; j++) acc[i][j] += p[i] * v[j];
        }
    }

    // epilogue: out2 = mass @ rel_values, then (acc + out2) / l
    __syncthreads();
    for (int it = tid; it < 64 * 16; it += 256) {
        const int r = it >> 4, c = (it & 15) * 4;
        float4 v = *(const float4*)&relV[r * HD_ + c];
        KP[r * SSTR + c + 0] = v.x;
        KP[r * SSTR + c + 1] = v.y;
        KP[r * SSTR + c + 2] = v.z;
        KP[r * SSTR + c + 3] = v.w;
    }
    __syncthreads();

    float o2[4][4];
    #pragma unroll
    for (int i = 0; i < 4; i++)
        #pragma unroll
        for (int j = 0; j < 4; j++) o2[i][j] = 0.f;

    #pragma unroll 8
    for (int u = 0; u < 64; u++) {
        float mm[4], rv[4];
        #pragma unroll
        for (int i = 0; i < 4; i++) mm[i] = mass[(ty * 4 + i) * SSTR + u];
        #pragma unroll
        for (int j = 0; j < 4; j++) rv[j] = KP[u * SSTR + tx * 4 + j];
        #pragma unroll
        for (int i = 0; i < 4; i++)
            #pragma unroll
            for (int j = 0; j < 4; j++) o2[i][j] += mm[i] * rv[j];
    }

    #pragma unroll
    for (int i = 0; i < 4; i++) {
        const int r = ty * 4 + i;
        const float linv = 1.f / l_s[r];
        #pragma unroll
        for (int j = 0; j < 4; j++)
            g_ret[headoff + (tbase + r) * HD_ + tx * 4 + j] =
                (acc[i][j] + o2[i][j]) * linv;
    }
}

#define ATTN_SMEM ((4 * 64 * SSTR + 4 * 64) * (int)sizeof(float))

extern "C" void kernel_launch(void* const* d_in, const int* in_sizes, int n_in,
                              void* d_out, int out_size)
{
    const float* x       = (const float*)d_in[0];
    const int*   rel     = (const int*)  d_in[1];
    const float* w_attn  = (const float*)d_in[2];
    const float* b_attn  = (const float*)d_in[3];
    const float* w_proj  = (const float*)d_in[4];
    const float* b_proj  = (const float*)d_in[5];
    const float* rel_w   = (const float*)d_in[6];
    const float* rel_v   = (const float*)d_in[7];
    const int*   rel_ids = (const int*)  d_in[8];
    float*       out     = (float*)d_out;

    cudaFuncSetAttribute(attn_kernel,
                         cudaFuncAttributeMaxDynamicSharedMemorySize, ATTN_SMEM);

    qkv_gemm<<<dim3(24, 32), 256>>>(x, w_attn, b_attn);
    attn_kernel<<<dim3(16, 16, 4), 256, ATTN_SMEM>>>(rel, rel_w, rel_v, rel_ids);
    proj_gemm<<<dim3(8, 32), 256>>>(w_proj, b_proj, out);
}

// round 9
// speedup vs baseline: 1.1289x; 1.1289x over previous
#include <cuda_runtime.h>
#include <mma.h>

using namespace nvcuda;

#define B_   4
#define T_   1024
#define NX_  1024
#define NH_  16
#define HD_  64

// Scratch (static device globals: allocation-free per harness rules)
__device__ float g_q  [B_ * NH_ * T_ * HD_];
__device__ float g_k  [B_ * NH_ * T_ * HD_];
__device__ float g_v  [B_ * NH_ * T_ * HD_];
__device__ float g_ret[B_ * NH_ * T_ * HD_];

// ---------------------------------------------------------------------------
// tf32 WMMA GEMM tiles: CTA 128x128, 8 warps (2 in N x 4 in M),
// warp tile 32x64 = 2x4 fragments of 16x16, K-step 16 (2 wmma-k of 8).
// smem (dynamic, 67584 B): double-buffered A[128][20], B[16][132];
// whole area reused as C-stage [128][132] in the epilogue.
// ---------------------------------------------------------------------------
#define KCP 20    // A row stride (16 + 4 pad)
#define NSP 132   // B / stage row stride (128 + 4 pad)
#define GEMM_SMEM (128 * NSP * 4)  // 67584 bytes

#define F2T(x) wmma::__float_to_tf32(x)

typedef wmma::fragment<wmma::matrix_a, 16, 16, 8, wmma::precision::tf32, wmma::row_major> FragA;
typedef wmma::fragment<wmma::matrix_b, 16, 16, 8, wmma::precision::tf32, wmma::row_major> FragB;
typedef wmma::fragment<wmma::accumulator, 16, 16, 8, float> FragC;

// ---------------------------------------------------------------------------
// GEMM 1: qkv = x @ w_attn + b_attn -> scatter into g_q/g_k/g_v [B,H,T,D]
// M=4096, N=3072, K=1024.
// ---------------------------------------------------------------------------
__global__ __launch_bounds__(256) void qkv_gemm(const float* __restrict__ X,
                                                const float* __restrict__ W,
                                                const float* __restrict__ bias)
{
    extern __shared__ float sm[];
    float* Asb[2] = {sm,        sm + 4672};
    float* Bsb[2] = {sm + 2560, sm + 7232};

    const int tid  = threadIdx.x;
    const int warp = tid >> 5;
    const int wm0  = (warp & 3) * 32;   // warp row offset in tile
    const int wn0  = (warp >> 2) * 64;  // warp col offset in tile
    const int m0 = blockIdx.y * 128, n0 = blockIdx.x * 128;

    // A cooperative-load indices: 128x16 floats = 512 float4, 2 per thread
    const int ar0 = tid >> 2;              // 0..63
    const int ac4 = (tid & 3) * 4;         // 0,4,8,12
    // B: 16x128 floats = 512 float4, 2 per thread
    const int br0 = tid >> 5;              // 0..7
    const int bc4 = (tid & 31) * 4;        // 0..124

    const float* aptr = &X[ac4];
    const float* bptr = &W[n0 + bc4];

    FragC acc[2][4];
    #pragma unroll
    for (int i = 0; i < 2; i++)
        #pragma unroll
        for (int j = 0; j < 4; j++) wmma::fill_fragment(acc[i][j], 0.f);

    // prologue: tile 0 -> buffer 0
    {
        float4 a0 = *(const float4*)&aptr[(m0 + ar0) * 1024];
        float4 a1 = *(const float4*)&aptr[(m0 + ar0 + 64) * 1024];
        float4 b0 = *(const float4*)&bptr[br0 * 3072];
        float4 b1 = *(const float4*)&bptr[(br0 + 8) * 3072];
        float* As = Asb[0];
        float* Bs = Bsb[0];
        As[ar0 * KCP + ac4 + 0] = F2T(a0.x); As[ar0 * KCP + ac4 + 1] = F2T(a0.y);
        As[ar0 * KCP + ac4 + 2] = F2T(a0.z); As[ar0 * KCP + ac4 + 3] = F2T(a0.w);
        As[(ar0 + 64) * KCP + ac4 + 0] = F2T(a1.x); As[(ar0 + 64) * KCP + ac4 + 1] = F2T(a1.y);
        As[(ar0 + 64) * KCP + ac4 + 2] = F2T(a1.z); As[(ar0 + 64) * KCP + ac4 + 3] = F2T(a1.w);
        Bs[br0 * NSP + bc4 + 0] = F2T(b0.x); Bs[br0 * NSP + bc4 + 1] = F2T(b0.y);
        Bs[br0 * NSP + bc4 + 2] = F2T(b0.z); Bs[br0 * NSP + bc4 + 3] = F2T(b0.w);
        Bs[(br0 + 8) * NSP + bc4 + 0] = F2T(b1.x); Bs[(br0 + 8) * NSP + bc4 + 1] = F2T(b1.y);
        Bs[(br0 + 8) * NSP + bc4 + 2] = F2T(b1.z); Bs[(br0 + 8) * NSP + bc4 + 3] = F2T(b1.w);
    }
    __syncthreads();

    int cur = 0;
    for (int k0 = 0; k0 < 1024; k0 += 16) {
        const int nxt = cur ^ 1;
        const bool has = (k0 + 16) < 1024;
        float4 a0, a1, b0, b1;
        if (has) {
            const int kn = k0 + 16;
            a0 = *(const float4*)&aptr[(m0 + ar0) * 1024 + kn];
            a1 = *(const float4*)&aptr[(m0 + ar0 + 64) * 1024 + kn];
            b0 = *(const float4*)&bptr[(kn + br0) * 3072];
            b1 = *(const float4*)&bptr[(kn + br0 + 8) * 3072];
        }

        const float* As = Asb[cur];
        const float* Bs = Bsb[cur];
        #pragma unroll
        for (int kk = 0; kk < 2; kk++) {
            FragA af[2];
            FragB bf[4];
            #pragma unroll
            for (int i = 0; i < 2; i++)
                wmma::load_matrix_sync(af[i], &As[(wm0 + i * 16) * KCP + kk * 8], KCP);
            #pragma unroll
            for (int j = 0; j < 4; j++)
                wmma::load_matrix_sync(bf[j], &Bs[(kk * 8) * NSP + wn0 + j * 16], NSP);
            #pragma unroll
            for (int i = 0; i < 2; i++)
                #pragma unroll
                for (int j = 0; j < 4; j++)
                    wmma::mma_sync(acc[i][j], af[i], bf[j], acc[i][j]);
        }

        if (has) {
            float* An = Asb[nxt];
            float* Bn = Bsb[nxt];
            An[ar0 * KCP + ac4 + 0] = F2T(a0.x); An[ar0 * KCP + ac4 + 1] = F2T(a0.y);
            An[ar0 * KCP + ac4 + 2] = F2T(a0.z); An[ar0 * KCP + ac4 + 3] = F2T(a0.w);
            An[(ar0 + 64) * KCP + ac4 + 0] = F2T(a1.x); An[(ar0 + 64) * KCP + ac4 + 1] = F2T(a1.y);
            An[(ar0 + 64) * KCP + ac4 + 2] = F2T(a1.z); An[(ar0 + 64) * KCP + ac4 + 3] = F2T(a1.w);
            Bn[br0 * NSP + bc4 + 0] = F2T(b0.x); Bn[br0 * NSP + bc4 + 1] = F2T(b0.y);
            Bn[br0 * NSP + bc4 + 2] = F2T(b0.z); Bn[br0 * NSP + bc4 + 3] = F2T(b0.w);
            Bn[(br0 + 8) * NSP + bc4 + 0] = F2T(b1.x); Bn[(br0 + 8) * NSP + bc4 + 1] = F2T(b1.y);
            Bn[(br0 + 8) * NSP + bc4 + 2] = F2T(b1.z); Bn[(br0 + 8) * NSP + bc4 + 3] = F2T(b1.w);
        }
        __syncthreads();
        cur = nxt;
    }

    // epilogue: stage C in smem, then scatter with bias
    #pragma unroll
    for (int i = 0; i < 2; i++)
        #pragma unroll
        for (int j = 0; j < 4; j++)
            wmma::store_matrix_sync(&sm[(wm0 + i * 16) * NSP + wn0 + j * 16],
                                    acc[i][j], NSP, wmma::mem_row_major);
    __syncthreads();

    for (int it = tid; it < 128 * 128; it += 256) {
        const int mi = it >> 7, ni = it & 127;
        const int m = m0 + mi, n = n0 + ni;
        const int b = m >> 10, t = m & 1023;
        float c = sm[mi * NSP + ni] + bias[n];
        const int which = n >> 10;
        const int rem = n & 1023;
        const int h = rem >> 6, d = rem & 63;
        float* dst = (which == 0) ? g_q : (which == 1) ? g_k : g_v;
        dst[((b * NH_ + h) * T_ + t) * HD_ + d] = c;
    }
}

// ---------------------------------------------------------------------------
// GEMM 2: out = ret_transposed @ w_proj + b_proj
// A gathered from g_ret [B,H,T,D] with k = h*64+d. M=4096, N=1024, K=1024.
// ---------------------------------------------------------------------------
__global__ __launch_bounds__(256) void proj_gemm(const float* __restrict__ W,
                                                 const float* __restrict__ bias,
                                                 float* __restrict__ out)
{
    extern __shared__ float sm[];
    float* Asb[2] = {sm,        sm + 4672};
    float* Bsb[2] = {sm + 2560, sm + 7232};

    const int tid  = threadIdx.x;
    const int warp = tid >> 5;
    const int wm0  = (warp & 3) * 32;
    const int wn0  = (warp >> 2) * 64;
    const int m0 = blockIdx.y * 128, n0 = blockIdx.x * 128;

    const int ar0 = tid >> 2;
    const int ac4 = (tid & 3) * 4;
    const int br0 = tid >> 5;
    const int bc4 = (tid & 31) * 4;

    // A rows: m = m0 + ar0 (+64); k = h*64+d, 4-wide never crosses h boundary
    const int mA0 = m0 + ar0,      bA0 = mA0 >> 10, tA0 = mA0 & 1023;
    const int mA1 = m0 + ar0 + 64, bA1 = mA1 >> 10, tA1 = mA1 & 1023;
    const float* aret0 = &g_ret[(bA0 * NH_ * T_ + tA0) * HD_];
    const float* aret1 = &g_ret[(bA1 * NH_ * T_ + tA1) * HD_];
    const float* bptr  = &W[n0 + bc4];

    FragC acc[2][4];
    #pragma unroll
    for (int i = 0; i < 2; i++)
        #pragma unroll
        for (int j = 0; j < 4; j++) wmma::fill_fragment(acc[i][j], 0.f);

    {
        const int k = ac4;
        const int h = k >> 6, d = k & 63;
        float4 a0 = *(const float4*)&aret0[h * T_ * HD_ + d];
        float4 a1 = *(const float4*)&aret1[h * T_ * HD_ + d];
        float4 b0 = *(const float4*)&bptr[br0 * 1024];
        float4 b1 = *(const float4*)&bptr[(br0 + 8) * 1024];
        float* As = Asb[0];
        float* Bs = Bsb[0];
        As[ar0 * KCP + ac4 + 0] = F2T(a0.x); As[ar0 * KCP + ac4 + 1] = F2T(a0.y);
        As[ar0 * KCP + ac4 + 2] = F2T(a0.z); As[ar0 * KCP + ac4 + 3] = F2T(a0.w);
        As[(ar0 + 64) * KCP + ac4 + 0] = F2T(a1.x); As[(ar0 + 64) * KCP + ac4 + 1] = F2T(a1.y);
        As[(ar0 + 64) * KCP + ac4 + 2] = F2T(a1.z); As[(ar0 + 64) * KCP + ac4 + 3] = F2T(a1.w);
        Bs[br0 * NSP + bc4 + 0] = F2T(b0.x); Bs[br0 * NSP + bc4 + 1] = F2T(b0.y);
        Bs[br0 * NSP + bc4 + 2] = F2T(b0.z); Bs[br0 * NSP + bc4 + 3] = F2T(b0.w);
        Bs[(br0 + 8) * NSP + bc4 + 0] = F2T(b1.x); Bs[(br0 + 8) * NSP + bc4 + 1] = F2T(b1.y);
        Bs[(br0 + 8) * NSP + bc4 + 2] = F2T(b1.z); Bs[(br0 + 8) * NSP + bc4 + 3] = F2T(b1.w);
    }
    __syncthreads();

    int cur = 0;
    for (int k0 = 0; k0 < 1024; k0 += 16) {
        const int nxt = cur ^ 1;
        const bool has = (k0 + 16) < 1024;
        float4 a0, a1, b0, b1;
        if (has) {
            const int k = k0 + 16 + ac4;
            const int h = k >> 6, d = k & 63;
            a0 = *(const float4*)&aret0[h * T_ * HD_ + d];
            a1 = *(const float4*)&aret1[h * T_ * HD_ + d];
            b0 = *(const float4*)&bptr[(k0 + 16 + br0) * 1024];
            b1 = *(const float4*)&bptr[(k0 + 16 + br0 + 8) * 1024];
        }

        const float* As = Asb[cur];
        const float* Bs = Bsb[cur];
        #pragma unroll
        for (int kk = 0; kk < 2; kk++) {
            FragA af[2];
            FragB bf[4];
            #pragma unroll
            for (int i = 0; i < 2; i++)
                wmma::load_matrix_sync(af[i], &As[(wm0 + i * 16) * KCP + kk * 8], KCP);
            #pragma unroll
            for (int j = 0; j < 4; j++)
                wmma::load_matrix_sync(bf[j], &Bs[(kk * 8) * NSP + wn0 + j * 16], NSP);
            #pragma unroll
            for (int i = 0; i < 2; i++)
                #pragma unroll
                for (int j = 0; j < 4; j++)
                    wmma::mma_sync(acc[i][j], af[i], bf[j], acc[i][j]);
        }

        if (has) {
            float* An = Asb[nxt];
            float* Bn = Bsb[nxt];
            An[ar0 * KCP + ac4 + 0] = F2T(a0.x); An[ar0 * KCP + ac4 + 1] = F2T(a0.y);
            An[ar0 * KCP + ac4 + 2] = F2T(a0.z); An[ar0 * KCP + ac4 + 3] = F2T(a0.w);
            An[(ar0 + 64) * KCP + ac4 + 0] = F2T(a1.x); An[(ar0 + 64) * KCP + ac4 + 1] = F2T(a1.y);
            An[(ar0 + 64) * KCP + ac4 + 2] = F2T(a1.z); An[(ar0 + 64) * KCP + ac4 + 3] = F2T(a1.w);
            Bn[br0 * NSP + bc4 + 0] = F2T(b0.x); Bn[br0 * NSP + bc4 + 1] = F2T(b0.y);
            Bn[br0 * NSP + bc4 + 2] = F2T(b0.z); Bn[br0 * NSP + bc4 + 3] = F2T(b0.w);
            Bn[(br0 + 8) * NSP + bc4 + 0] = F2T(b1.x); Bn[(br0 + 8) * NSP + bc4 + 1] = F2T(b1.y);
            Bn[(br0 + 8) * NSP + bc4 + 2] = F2T(b1.z); Bn[(br0 + 8) * NSP + bc4 + 3] = F2T(b1.w);
        }
        __syncthreads();
        cur = nxt;
    }

    #pragma unroll
    for (int i = 0; i < 2; i++)
        #pragma unroll
        for (int j = 0; j < 4; j++)
            wmma::store_matrix_sync(&sm[(wm0 + i * 16) * NSP + wn0 + j * 16],
                                    acc[i][j], NSP, wmma::mem_row_major);
    __syncthreads();

    for (int it = tid; it < 128 * 128; it += 256) {
        const int mi = it >> 7, ni = it & 127;
        const int m = m0 + mi, n = n0 + ni;
        out[m * 1024 + n] = sm[mi * NSP + ni] + bias[n];
    }
}

// ---------------------------------------------------------------------------
// Flash attention with relative bias + bucketed relative-values term.
// (unchanged; known LDS-bound — planned rework after next successful bench)
// ---------------------------------------------------------------------------
#define SSTR 65

__global__ __launch_bounds__(256) void attn_kernel(const int*   __restrict__ relB,
                                                   const float* __restrict__ relW,
                                                   const float* __restrict__ relV,
                                                   const int*   __restrict__ relIds)
{
    extern __shared__ float sm[];
    float* Qs   = sm;
    float* KP   = Qs  + 64 * SSTR;
    float* Vs   = KP  + 64 * SSTR;
    float* mass = Vs  + 64 * SSTR;
    float* relw = mass + 64 * SSTR;
    float* m_s  = relw + 64;
    float* l_s  = m_s + 64;
    float* sc_s = l_s + 64;

    const int tid = threadIdx.x;
    const int tx = tid & 15, ty = tid >> 4;
    const int jb = blockIdx.x;
    const int h  = blockIdx.y;
    const int b  = blockIdx.z;
    const int tbase = jb * 64;

    const int headoff = ((b * NH_ + h) * T_) * HD_;
    const float* qptr = g_q + headoff;
    const float* kptr = g_k + headoff;
    const float* vptr = g_v + headoff;

    for (int it = tid; it < 64 * SSTR; it += 256) mass[it] = 0.f;
    if (tid < 64) {
        m_s[tid] = -1e30f;
        l_s[tid] = 0.f;
        relw[tid] = relW[tid * NH_ + h];
    }
    for (int it = tid; it < 64 * 16; it += 256) {
        const int r = it >> 4, c = (it & 15) * 4;
        float4 v = *(const float4*)&qptr[(tbase + r) * HD_ + c];
        Qs[r * SSTR + c + 0] = v.x;
        Qs[r * SSTR + c + 1] = v.y;
        Qs[r * SSTR + c + 2] = v.z;
        Qs[r * SSTR + c + 3] = v.w;
    }

    float acc[4][4];
    #pragma unroll
    for (int i = 0; i < 4; i++)
        #pragma unroll
        for (int j = 0; j < 4; j++) acc[i][j] = 0.f;

    for (int sb = 0; sb <= jb; sb++) {
        const int sbase = sb * 64;
        __syncthreads();

        for (int it = tid; it < 64 * 16; it += 256) {
            const int r = it >> 4, c = (it & 15) * 4;
            float4 kv = *(const float4*)&kptr[(sbase + r) * HD_ + c];
            float4 vv = *(const float4*)&vptr[(sbase + r) * HD_ + c];
            KP[r * SSTR + c + 0] = kv.x; KP[r * SSTR + c + 1] = kv.y;
            KP[r * SSTR + c + 2] = kv.z; KP[r * SSTR + c + 3] = kv.w;
            Vs[r * SSTR + c + 0] = vv.x; Vs[r * SSTR + c + 1] = vv.y;
            Vs[r * SSTR + c + 2] = vv.z; Vs[r * SSTR + c + 3] = vv.w;
        }
        __syncthreads();

        float s[4][4];
        #pragma unroll
        for (int i = 0; i < 4; i++)
            #pragma unroll
            for (int j = 0; j < 4; j++) s[i][j] = 0.f;

        #pragma unroll 8
        for (int d = 0; d < 64; d++) {
            float q[4], k[4];
            #pragma unroll
            for (int i = 0; i < 4; i++) q[i] = Qs[(ty * 4 + i) * SSTR + d];
            #pragma unroll
            for (int j = 0; j < 4; j++) k[j] = KP[(tx * 4 + j) * SSTR + d];
            #pragma unroll
            for (int i = 0; i < 4; i++)
                #pragma unroll
                for (int j = 0; j < 4; j++) s[i][j] += q[i] * k[j];
        }
        __syncthreads();

        #pragma unroll
        for (int i = 0; i < 4; i++) {
            const int t = tbase + ty * 4 + i;
            const int4 rb = *(const int4*)&relB[(b * T_ + t) * T_ + sbase + tx * 4];
            const int rbv[4] = {rb.x, rb.y, rb.z, rb.w};
            #pragma unroll
            for (int j = 0; j < 4; j++) {
                const int sg = sbase + tx * 4 + j;
                if (sg <= t)
                    s[i][j] = s[i][j] * 0.125f + relw[rbv[j]];
                else
                    s[i][j] = -1e30f;
            }
        }

        float rmax[4];
        #pragma unroll
        for (int i = 0; i < 4; i++) {
            float v = s[i][0];
            v = fmaxf(v, s[i][1]); v = fmaxf(v, s[i][2]); v = fmaxf(v, s[i][3]);
            rmax[i] = v;
        }
        #pragma unroll
        for (int o = 8; o >= 1; o >>= 1)
            #pragma unroll
            for (int i = 0; i < 4; i++)
                rmax[i] = fmaxf(rmax[i], __shfl_xor_sync(0xffffffffu, rmax[i], o, 16));

        if (tx == 0) {
            #pragma unroll
            for (int i = 0; i < 4; i++) {
                const int r = ty * 4 + i;
                float mn = fmaxf(m_s[r], rmax[i]);
                sc_s[r] = __expf(m_s[r] - mn);
                m_s[r] = mn;
            }
        }
        __syncwarp();

        float rsum[4];
        #pragma unroll
        for (int i = 0; i < 4; i++) {
            const float mi = m_s[ty * 4 + i];
            float acc_s = 0.f;
            #pragma unroll
            for (int j = 0; j < 4; j++) {
                float p = __expf(s[i][j] - mi);
                s[i][j] = p;
                acc_s += p;
            }
            rsum[i] = acc_s;
        }
        #pragma unroll
        for (int o = 8; o >= 1; o >>= 1)
            #pragma unroll
            for (int i = 0; i < 4; i++)
                rsum[i] += __shfl_xor_sync(0xffffffffu, rsum[i], o, 16);

        if (tx == 0) {
            #pragma unroll
            for (int i = 0; i < 4; i++) {
                const int r = ty * 4 + i;
                l_s[r] = l_s[r] * sc_s[r] + rsum[i];
            }
        }

        #pragma unroll
        for (int i = 0; i < 4; i++) {
            const float sc = sc_s[ty * 4 + i];
            #pragma unroll
            for (int j = 0; j < 4; j++) {
                acc[i][j] *= sc;
                mass[(ty * 4 + i) * SSTR + tx * 4 + j] *= sc;
            }
        }

        #pragma unroll
        for (int i = 0; i < 4; i++)
            #pragma unroll
            for (int j = 0; j < 4; j++)
                KP[(ty * 4 + i) * SSTR + tx * 4 + j] = s[i][j];
        __syncwarp();

        #pragma unroll
        for (int i = 0; i < 4; i++) {
            const int t = tbase + ty * 4 + i;
            const int4 ri = *(const int4*)&relIds[t * T_ + sbase + tx * 4];
            const int riv[4] = {ri.x, ri.y, ri.z, ri.w};
            #pragma unroll
            for (int j = 0; j < 4; j++) {
                const int sg = sbase + tx * 4 + j;
                if (sg <= t)
                    atomicAdd(&mass[(ty * 4 + i) * SSTR + riv[j]], s[i][j]);
            }
        }

        #pragma unroll 8
        for (int ss = 0; ss < 64; ss++) {
            float p[4], v[4];
            #pragma unroll
            for (int i = 0; i < 4; i++) p[i] = KP[(ty * 4 + i) * SSTR + ss];
            #pragma unroll
            for (int j = 0; j < 4; j++) v[j] = Vs[ss * SSTR + tx * 4 + j];
            #pragma unroll
            for (int i = 0; i < 4; i++)
                #pragma unroll
                for (int j = 0; j < 4; j++) acc[i][j] += p[i] * v[j];
        }
    }

    __syncthreads();
    for (int it = tid; it < 64 * 16; it += 256) {
        const int r = it >> 4, c = (it & 15) * 4;
        float4 v = *(const float4*)&relV[r * HD_ + c];
        KP[r * SSTR + c + 0] = v.x;
        KP[r * SSTR + c + 1] = v.y;
        KP[r * SSTR + c + 2] = v.z;
        KP[r * SSTR + c + 3] = v.w;
    }
    __syncthreads();

    float o2[4][4];
    #pragma unroll
    for (int i = 0; i < 4; i++)
        #pragma unroll
        for (int j = 0; j < 4; j++) o2[i][j] = 0.f;

    #pragma unroll 8
    for (int u = 0; u < 64; u++) {
        float mm[4], rv[4];
        #pragma unroll
        for (int i = 0; i < 4; i++) mm[i] = mass[(ty * 4 + i) * SSTR + u];
        #pragma unroll
        for (int j = 0; j < 4; j++) rv[j] = KP[u * SSTR + tx * 4 + j];
        #pragma unroll
        for (int i = 0; i < 4; i++)
            #pragma unroll
            for (int j = 0; j < 4; j++) o2[i][j] += mm[i] * rv[j];
    }

    #pragma unroll
    for (int i = 0; i < 4; i++) {
        const int r = ty * 4 + i;
        const float linv = 1.f / l_s[r];
        #pragma unroll
        for (int j = 0; j < 4; j++)
            g_ret[headoff + (tbase + r) * HD_ + tx * 4 + j] =
                (acc[i][j] + o2[i][j]) * linv;
    }
}

#define ATTN_SMEM ((4 * 64 * SSTR + 4 * 64) * (int)sizeof(float))

extern "C" void kernel_launch(void* const* d_in, const int* in_sizes, int n_in,
                              void* d_out, int out_size)
{
    const float* x       = (const float*)d_in[0];
    const int*   rel     = (const int*)  d_in[1];
    const float* w_attn  = (const float*)d_in[2];
    const float* b_attn  = (const float*)d_in[3];
    const float* w_proj  = (const float*)d_in[4];
    const float* b_proj  = (const float*)d_in[5];
    const float* rel_w   = (const float*)d_in[6];
    const float* rel_v   = (const float*)d_in[7];
    const int*   rel_ids = (const int*)  d_in[8];
    float*       out     = (float*)d_out;

    cudaFuncSetAttribute(qkv_gemm,
                         cudaFuncAttributeMaxDynamicSharedMemorySize, GEMM_SMEM);
    cudaFuncSetAttribute(proj_gemm,
                         cudaFuncAttributeMaxDynamicSharedMemorySize, GEMM_SMEM);
    cudaFuncSetAttribute(attn_kernel,
                         cudaFuncAttributeMaxDynamicSharedMemorySize, ATTN_SMEM);

    qkv_gemm<<<dim3(24, 32), 256, GEMM_SMEM>>>(x, w_attn, b_attn);
    attn_kernel<<<dim3(16, 16, 4), 256, ATTN_SMEM>>>(rel, rel_w, rel_v, rel_ids);
    proj_gemm<<<dim3(8, 32), 256, GEMM_SMEM>>>(w_proj, b_proj, out);
}